// round 11
// baseline (speedup 1.0000x reference)
#include <cuda_runtime.h>
#include <cuda_bf16.h>
#include <cuda_fp16.h>
#include <cstdint>
#include <mma.h>

using namespace nvcuda;

#define D      64
#define NMAX   100000
#define EMAX   2000000
#define CAP    128         // max slots per node
#define GB     64          // nodes per gemm block

// Scratch (allocation-free rule: __device__ globals)
__device__ __align__(16) __half2 g_hs[(size_t)NMAX * 32];  // h * dinv[src], fp16
__device__ int g_cnt[NMAX];                 // degree counters / cursors
__device__ int g_slot[(size_t)NMAX * CAP];  // src per edge, bucketed by dst

// ---------------------------------------------------------------------------
__device__ __forceinline__ int clampi(long long v, int n) {
    if (v < 0)  v = 0;
    if (v >= n) v = n - 1;
    return (int)v;
}

// Per-block dtype detect: warp 0 ballots first 256 int64-interpreted values.
__device__ __forceinline__ int block_detect(const void* ei, int E, int n) {
    __shared__ int smode;
    if (threadIdx.x < 32) {
        const long long* p = (const long long*)ei;
        int lim = E < 256 ? E : 256;
        bool bad = false;
        for (int k = threadIdx.x; k < lim; k += 32) {
            long long v = p[k];
            if (v < 0 || v >= (long long)n) bad = true;
        }
        unsigned m = __ballot_sync(0xffffffffu, bad);
        if (threadIdx.x == 0) smode = m ? 1 : 0;
    }
    __syncthreads();
    return smode;
}

// Direct bucket fill: 2 edges per thread, vectorized index loads.
// Atomic return value = slot index.
__global__ void k_fill(const void* __restrict__ ei, int E, int n) {
    int mode = block_detect(ei, E, n);
    int t = blockIdx.x * blockDim.x + threadIdx.x;
    int e0 = t * 2;
    if (e0 >= E) return;
    bool pair = (e0 + 1 < E);

    int s0, s1 = 0, d0, d1 = 0;
    if (mode == 0) {
        const long long* p = (const long long*)ei;
        if (pair) {
            longlong2 sv = ((const longlong2*)p)[t];
            longlong2 dv = *(const longlong2*)(p + (size_t)E + e0);
            s0 = clampi(sv.x, n); s1 = clampi(sv.y, n);
            d0 = clampi(dv.x, n); d1 = clampi(dv.y, n);
        } else {
            s0 = clampi(p[e0], n);
            d0 = clampi(p[(size_t)E + e0], n);
        }
    } else {
        const int* p = (const int*)ei;
        if (pair) {
            int2 sv = ((const int2*)p)[t];
            int2 dv = *(const int2*)(p + (size_t)E + e0);
            s0 = clampi(sv.x, n); s1 = clampi(sv.y, n);
            d0 = clampi(dv.x, n); d1 = clampi(dv.y, n);
        } else {
            s0 = clampi(p[e0], n);
            d0 = clampi(p[(size_t)E + e0], n);
        }
    }

    int c0 = atomicAdd(&g_cnt[d0], 1);
    if (c0 < CAP) g_slot[(size_t)d0 * CAP + c0] = s0;
    if (pair) {
        int c1 = atomicAdd(&g_cnt[d1], 1);
        if (c1 < CAP) g_slot[(size_t)d1 * CAP + c1] = s1;
    }
}

// ---------------------------------------------------------------------------
// GEMM + out init via tf32 wmma (m16n16k8). 64 nodes per block (dyn smem),
// 8 warps: warp = (nrbase 0..1, nc 0..3), rows nrbase & nrbase+2.
// tf32 conversion hoisted to the staging phase (smem holds tf32-rounded fp32),
// so the inner loop is pure LDS + MMA.
//   dinv   = rsqrt(cnt+1)                  (computed inline)
//   hs[n]  = (x[n] @ Wg) * dinv[n]          (stored fp16)
//   out[n] = pos[n] @ Wp + b_pos + b_gcn + hs[n]*dinv[n]   (self-loop, fp32)
__global__ __launch_bounds__(256) void k_gemm_init(
    const float* __restrict__ x, const float* __restrict__ pos,
    const float* __restrict__ Wg, const float* __restrict__ bg,
    const float* __restrict__ Wp, const float* __restrict__ bp,
    float* __restrict__ out, int n)
{
    extern __shared__ float smem_dyn[];
    float* sWg = smem_dyn;           // 4096
    float* sWp = sWg + D * D;        // 4096
    float* sX  = sWp + D * D;        // 4096 (GB*D)
    float* sP  = sX + GB * D;        // 4096

    int tid  = threadIdx.x;
    int warp = tid >> 5;

    // stage weights (1024 float4 each, 4 per thread), tf32-rounded
    {
        const float4* Wg4 = (const float4*)Wg;
        const float4* Wp4 = (const float4*)Wp;
        float4* sWg4 = (float4*)sWg;
        float4* sWp4 = (float4*)sWp;
#pragma unroll
        for (int i = 0; i < 4; i++) {
            float4 a = Wg4[tid + 256 * i];
            float4 b = Wp4[tid + 256 * i];
            a.x = wmma::__float_to_tf32(a.x); a.y = wmma::__float_to_tf32(a.y);
            a.z = wmma::__float_to_tf32(a.z); a.w = wmma::__float_to_tf32(a.w);
            b.x = wmma::__float_to_tf32(b.x); b.y = wmma::__float_to_tf32(b.y);
            b.z = wmma::__float_to_tf32(b.z); b.w = wmma::__float_to_tf32(b.w);
            sWg4[tid + 256 * i] = a;
            sWp4[tid + 256 * i] = b;
        }
    }
    // stage inputs: 1024 float4 each, 4 per thread, tf32-rounded (clamp oob)
    {
        int base = blockIdx.x * GB;
        float4* sX4 = (float4*)sX;
        float4* sP4 = (float4*)sP;
#pragma unroll
        for (int i = 0; i < 4; i++) {
            int idx = tid + 256 * i;            // float4 index in tile
            int ln  = idx >> 4;                 // node 0..63
            int cg  = idx & 15;
            int gn  = base + ln;
            if (gn >= n) gn = n - 1;
            float4 a = ((const float4*)x)[(size_t)gn * 16 + cg];
            float4 b = ((const float4*)pos)[(size_t)gn * 16 + cg];
            a.x = wmma::__float_to_tf32(a.x); a.y = wmma::__float_to_tf32(a.y);
            a.z = wmma::__float_to_tf32(a.z); a.w = wmma::__float_to_tf32(a.w);
            b.x = wmma::__float_to_tf32(b.x); b.y = wmma::__float_to_tf32(b.y);
            b.z = wmma::__float_to_tf32(b.z); b.w = wmma::__float_to_tf32(b.w);
            sX4[idx] = a;
            sP4[idx] = b;
        }
    }
    __syncthreads();

    int nrb = warp >> 2;
    int nc  = warp & 3;

    wmma::fragment<wmma::accumulator, 16, 16, 8, float> cG[2], cP[2];
    wmma::fill_fragment(cG[0], 0.0f);
    wmma::fill_fragment(cP[0], 0.0f);
    wmma::fill_fragment(cG[1], 0.0f);
    wmma::fill_fragment(cP[1], 0.0f);

#pragma unroll
    for (int k = 0; k < 8; k++) {
        wmma::fragment<wmma::matrix_b, 16, 16, 8, wmma::precision::tf32, wmma::row_major> bG, bP;
        wmma::load_matrix_sync(bG, &sWg[(k * 8) * D + nc * 16], D);
        wmma::load_matrix_sync(bP, &sWp[(k * 8) * D + nc * 16], D);
#pragma unroll
        for (int r = 0; r < 2; r++) {
            int nr = nrb + 2 * r;
            wmma::fragment<wmma::matrix_a, 16, 16, 8, wmma::precision::tf32, wmma::row_major> aX, aP;
            wmma::load_matrix_sync(aX, &sX[(nr * 16) * D + k * 8], D);
            wmma::load_matrix_sync(aP, &sP[(nr * 16) * D + k * 8], D);
            wmma::mma_sync(cG[r], aX, bG, cG[r]);
            wmma::mma_sync(cP[r], aP, bP, cP[r]);
        }
    }

    __syncthreads();   // all input reads done before overwriting with C
#pragma unroll
    for (int r = 0; r < 2; r++) {
        int nr = nrb + 2 * r;
        wmma::store_matrix_sync(&sX[(nr * 16) * D + nc * 16], cG[r], D, wmma::mem_row_major);
        wmma::store_matrix_sync(&sP[(nr * 16) * D + nc * 16], cP[r], D, wmma::mem_row_major);
    }
    __syncthreads();

    // epilogue: 2 passes, thread = (node 0..31 + 32*pass, colgroup 0..7)
#pragma unroll
    for (int pass = 0; pass < 2; pass++) {
        int ln = (tid >> 3) + 32 * pass;
        int cg = tid & 7;              // 8 cols
        int gn = blockIdx.x * GB + ln;
        if (gn < n) {
            float di = rsqrtf((float)g_cnt[gn] + 1.0f);
            const float4* cg4 = (const float4*)&sX[ln * D + cg * 8];
            const float4* cp4 = (const float4*)&sP[ln * D + cg * 8];
            const float4* bg4 = (const float4*)&bg[cg * 8];
            const float4* bp4 = (const float4*)&bp[cg * 8];
#pragma unroll
            for (int h = 0; h < 2; h++) {
                float4 g4 = cg4[h], p4 = cp4[h], b1 = bg4[h], b2 = bp4[h];
                float4 hs;
                hs.x = g4.x * di; hs.y = g4.y * di; hs.z = g4.z * di; hs.w = g4.w * di;
                __half2 h0 = __floats2half2_rn(hs.x, hs.y);
                __half2 h1 = __floats2half2_rn(hs.z, hs.w);
                g_hs[(size_t)gn * 32 + (cg * 2 + h) * 2 + 0] = h0;
                g_hs[(size_t)gn * 32 + (cg * 2 + h) * 2 + 1] = h1;
                float4 o;
                o.x = p4.x + b1.x + b2.x + hs.x * di;
                o.y = p4.y + b1.y + b2.y + hs.y * di;
                o.z = p4.z + b1.z + b2.z + hs.z * di;
                o.w = p4.w + b1.w + b2.w + hs.w * di;
                ((float4*)out)[(size_t)gn * 16 + cg * 2 + h] = o;
            }
        }
    }
}

// ---------------------------------------------------------------------------
// Aggregate: one warp per node, TWO edges per load round.
// lanes 0-15: even edges, lanes 16-31: odd edges; lane covers 4 cols (8B).
// Full rounds of 8 unmasked, then ONE masked round of 8 (no dependent tail).
// Combine halves with shfl_xor(16); lanes 0-15 write float4.
//   out[node] += rsqrt(cnt+1) * sum_{src in slots[node]} hs[src]
__global__ __launch_bounds__(256) void k_agg(float* __restrict__ out, int n) {
    int warp = (blockIdx.x * blockDim.x + threadIdx.x) >> 5;
    int lane = threadIdx.x & 31;
    if (warp >= n) return;

    int cnt = g_cnt[warp];
    int deg = cnt < CAP ? cnt : CAP;
    const int* slots = &g_slot[(size_t)warp * CAP];
    int half  = lane >> 4;
    int sub   = lane & 15;

    const uint2* hs = (const uint2*)g_hs;   // 16 uint2 per node row (128B)
    float4 a = {0.f, 0.f, 0.f, 0.f};

    int j = 0;
    for (; j + 8 <= deg; j += 8) {
        int s[8];
#pragma unroll
        for (int u = 0; u < 8; u++) s[u] = slots[j + u];
#pragma unroll
        for (int u = 0; u < 4; u++) {
            int e = half ? s[2 * u + 1] : s[2 * u];
            uint2 v = hs[(size_t)e * 16 + sub];
            __half2 h0 = *reinterpret_cast<__half2*>(&v.x);
            __half2 h1 = *reinterpret_cast<__half2*>(&v.y);
            float2 f0 = __half22float2(h0);
            float2 f1 = __half22float2(h1);
            a.x += f0.x; a.y += f0.y; a.z += f1.x; a.w += f1.y;
        }
    }
    if (j < deg) {
        int   s[8];
        float m[8];
#pragma unroll
        for (int u = 0; u < 8; u++) {
            int jj = j + u;
            int idx = jj < deg ? jj : deg - 1;
            s[u] = slots[idx];
            m[u] = jj < deg ? 1.f : 0.f;
        }
#pragma unroll
        for (int u = 0; u < 4; u++) {
            int   e  = half ? s[2 * u + 1] : s[2 * u];
            float me = half ? m[2 * u + 1] : m[2 * u];
            uint2 v = hs[(size_t)e * 16 + sub];
            __half2 h0 = *reinterpret_cast<__half2*>(&v.x);
            __half2 h1 = *reinterpret_cast<__half2*>(&v.y);
            float2 f0 = __half22float2(h0);
            float2 f1 = __half22float2(h1);
            a.x = fmaf(me, f0.x, a.x);
            a.y = fmaf(me, f0.y, a.y);
            a.z = fmaf(me, f1.x, a.z);
            a.w = fmaf(me, f1.y, a.w);
        }
    }

    a.x += __shfl_xor_sync(0xffffffffu, a.x, 16);
    a.y += __shfl_xor_sync(0xffffffffu, a.y, 16);
    a.z += __shfl_xor_sync(0xffffffffu, a.z, 16);
    a.w += __shfl_xor_sync(0xffffffffu, a.w, 16);

    if (half == 0) {
        float w = rsqrtf((float)cnt + 1.0f);
        float4* o = (float4*)out + (size_t)warp * 16 + sub;
        float4 cur = *o;
        cur.x += w * a.x;
        cur.y += w * a.y;
        cur.z += w * a.z;
        cur.w += w * a.w;
        *o = cur;
    }
}

// ---------------------------------------------------------------------------
extern "C" void kernel_launch(void* const* d_in, const int* in_sizes, int n_in,
                              void* d_out, int out_size)
{
    // Identify inputs by size pattern (robust to harness reordering).
    int N = 100000, E = 1600000;
    int i_edge = 1;
    int feat[2] = {0, 2}, wmat[2], nw = 0, bias[2], nb = 0;
    for (int i = 0; i < n_in; i++) {
        int s = in_sizes[i];
        if (s == D * D)  { if (nw < 2) wmat[nw++] = i; }
        else if (s == D) { if (nb < 2) bias[nb++] = i; }
    }
    {
        int larges[3], nl = 0;
        for (int i = 0; i < n_in; i++) {
            int s = in_sizes[i];
            if (s != D * D && s != D) { if (nl < 3) larges[nl++] = i; }
        }
        if (nl == 3) {
            int s0 = in_sizes[larges[0]], s1 = in_sizes[larges[1]], s2 = in_sizes[larges[2]];
            int ie;
            if (s0 == s1)      ie = larges[2];
            else if (s0 == s2) ie = larges[1];
            else if (s1 == s2) ie = larges[0];
            else               ie = larges[1];
            i_edge = ie;
            int k = 0;
            for (int j = 0; j < 3; j++) if (larges[j] != ie) feat[k++] = larges[j];
            E = in_sizes[ie] / 2;
            N = in_sizes[feat[0]] / D;
        }
    }

    const float* x   = (const float*)d_in[feat[0]];
    const float* pos = (const float*)d_in[feat[1]];
    const void*  ei  = d_in[i_edge];
    const float* Wg  = (const float*)d_in[wmat[0]];
    const float* Wp  = (const float*)d_in[wmat[1]];
    const float* bg  = (const float*)d_in[bias[0]];
    const float* bp  = (const float*)d_in[bias[1]];
    float*       out = (float*)d_out;

    if (N > NMAX) N = NMAX;
    if (E > EMAX) E = EMAX;

    // zero degree counters via async memset (no kernel launch)
    void* cnt_ptr = nullptr;
    cudaGetSymbolAddress(&cnt_ptr, g_cnt);
    cudaMemsetAsync(cnt_ptr, 0, (size_t)N * sizeof(int));

    cudaFuncSetAttribute(k_gemm_init, cudaFuncAttributeMaxDynamicSharedMemorySize,
                         (int)(16384 * sizeof(float)));

    int nthreads_fill = (E + 1) / 2;
    k_fill<<<(nthreads_fill + 255) / 256, 256>>>(ei, E, N);
    k_gemm_init<<<(N + GB - 1) / GB, 256, 16384 * sizeof(float)>>>(x, pos, Wg, bg, Wp, bp, out, N);
    k_agg<<<(N * 32 + 255) / 256, 256>>>(out, N);
}

// round 13
// speedup vs baseline: 1.0172x; 1.0172x over previous
#include <cuda_runtime.h>
#include <cuda_bf16.h>
#include <cuda_fp16.h>
#include <cstdint>
#include <mma.h>

using namespace nvcuda;

#define D      64
#define NMAX   100000
#define EMAX   2000000
#define CAP    128         // max slots per node
#define GB     64          // nodes per gemm block

// Scratch (allocation-free rule: __device__ globals)
__device__ __align__(16) __half2 g_hs[(size_t)NMAX * 32];  // h = x@Wg (UNSCALED), fp16
__device__ int g_cnt[NMAX];                 // degree counters / cursors
__device__ int g_slot[(size_t)NMAX * CAP];  // src per edge, bucketed by dst

// ---------------------------------------------------------------------------
__device__ __forceinline__ int clampi(long long v, int n) {
    if (v < 0)  v = 0;
    if (v >= n) v = n - 1;
    return (int)v;
}

// Per-block dtype detect: warp 0 ballots first 256 int64-interpreted values.
__device__ __forceinline__ int block_detect(const void* ei, int E, int n) {
    __shared__ int smode;
    if (threadIdx.x < 32) {
        const long long* p = (const long long*)ei;
        int lim = E < 256 ? E : 256;
        bool bad = false;
        for (int k = threadIdx.x; k < lim; k += 32) {
            long long v = p[k];
            if (v < 0 || v >= (long long)n) bad = true;
        }
        unsigned m = __ballot_sync(0xffffffffu, bad);
        if (threadIdx.x == 0) smode = m ? 1 : 0;
    }
    __syncthreads();
    return smode;
}

// Direct bucket fill (R10 shape: 1 edge/thread). Atomic return = slot index.
__global__ void k_fill(const void* __restrict__ ei, int E, int n) {
    int mode = block_detect(ei, E, n);
    int e = blockIdx.x * blockDim.x + threadIdx.x;
    if (e < E) {
        int src, dst;
        if (mode == 0) {
            const long long* p = (const long long*)ei;
            src = clampi(p[e], n);
            dst = clampi(p[(size_t)E + e], n);
        } else {
            const int* p = (const int*)ei;
            src = clampi((long long)p[e], n);
            dst = clampi((long long)p[(size_t)E + e], n);
        }
        int c = atomicAdd(&g_cnt[dst], 1);
        if (c < CAP) g_slot[(size_t)dst * CAP + c] = src;
    }
}

// ---------------------------------------------------------------------------
// Pure dual GEMM (NO dependence on g_cnt -> runs concurrently with k_fill).
//   h[n]   = x[n] @ Wg                     (stored fp16, unscaled)
//   out[n] = pos[n] @ Wp + b_pos + b_gcn   (conv part added later by k_agg)
// tf32 wmma m16n16k8, 64 nodes/block, conversion hoisted to staging.
__global__ __launch_bounds__(256) void k_gemm_pure(
    const float* __restrict__ x, const float* __restrict__ pos,
    const float* __restrict__ Wg, const float* __restrict__ bg,
    const float* __restrict__ Wp, const float* __restrict__ bp,
    float* __restrict__ out, int n)
{
    extern __shared__ float smem_dyn[];
    float* sWg = smem_dyn;           // 4096
    float* sWp = sWg + D * D;        // 4096
    float* sX  = sWp + D * D;        // 4096 (GB*D)
    float* sP  = sX + GB * D;        // 4096

    int tid  = threadIdx.x;
    int warp = tid >> 5;

    // stage weights (1024 float4 each, 4 per thread), tf32-rounded
    {
        const float4* Wg4 = (const float4*)Wg;
        const float4* Wp4 = (const float4*)Wp;
        float4* sWg4 = (float4*)sWg;
        float4* sWp4 = (float4*)sWp;
#pragma unroll
        for (int i = 0; i < 4; i++) {
            float4 a = Wg4[tid + 256 * i];
            float4 b = Wp4[tid + 256 * i];
            a.x = wmma::__float_to_tf32(a.x); a.y = wmma::__float_to_tf32(a.y);
            a.z = wmma::__float_to_tf32(a.z); a.w = wmma::__float_to_tf32(a.w);
            b.x = wmma::__float_to_tf32(b.x); b.y = wmma::__float_to_tf32(b.y);
            b.z = wmma::__float_to_tf32(b.z); b.w = wmma::__float_to_tf32(b.w);
            sWg4[tid + 256 * i] = a;
            sWp4[tid + 256 * i] = b;
        }
    }
    // stage inputs: 1024 float4 each, 4 per thread, tf32-rounded (clamp oob)
    {
        int base = blockIdx.x * GB;
        float4* sX4 = (float4*)sX;
        float4* sP4 = (float4*)sP;
#pragma unroll
        for (int i = 0; i < 4; i++) {
            int idx = tid + 256 * i;            // float4 index in tile
            int ln  = idx >> 4;                 // node 0..63
            int cg  = idx & 15;
            int gn  = base + ln;
            if (gn >= n) gn = n - 1;
            float4 a = ((const float4*)x)[(size_t)gn * 16 + cg];
            float4 b = ((const float4*)pos)[(size_t)gn * 16 + cg];
            a.x = wmma::__float_to_tf32(a.x); a.y = wmma::__float_to_tf32(a.y);
            a.z = wmma::__float_to_tf32(a.z); a.w = wmma::__float_to_tf32(a.w);
            b.x = wmma::__float_to_tf32(b.x); b.y = wmma::__float_to_tf32(b.y);
            b.z = wmma::__float_to_tf32(b.z); b.w = wmma::__float_to_tf32(b.w);
            sX4[idx] = a;
            sP4[idx] = b;
        }
    }
    __syncthreads();

    int nrb = warp >> 2;
    int nc  = warp & 3;

    wmma::fragment<wmma::accumulator, 16, 16, 8, float> cG[2], cP[2];
    wmma::fill_fragment(cG[0], 0.0f);
    wmma::fill_fragment(cP[0], 0.0f);
    wmma::fill_fragment(cG[1], 0.0f);
    wmma::fill_fragment(cP[1], 0.0f);

#pragma unroll
    for (int k = 0; k < 8; k++) {
        wmma::fragment<wmma::matrix_b, 16, 16, 8, wmma::precision::tf32, wmma::row_major> bG, bP;
        wmma::load_matrix_sync(bG, &sWg[(k * 8) * D + nc * 16], D);
        wmma::load_matrix_sync(bP, &sWp[(k * 8) * D + nc * 16], D);
#pragma unroll
        for (int r = 0; r < 2; r++) {
            int nr = nrb + 2 * r;
            wmma::fragment<wmma::matrix_a, 16, 16, 8, wmma::precision::tf32, wmma::row_major> aX, aP;
            wmma::load_matrix_sync(aX, &sX[(nr * 16) * D + k * 8], D);
            wmma::load_matrix_sync(aP, &sP[(nr * 16) * D + k * 8], D);
            wmma::mma_sync(cG[r], aX, bG, cG[r]);
            wmma::mma_sync(cP[r], aP, bP, cP[r]);
        }
    }

    __syncthreads();   // all input reads done before overwriting with C
#pragma unroll
    for (int r = 0; r < 2; r++) {
        int nr = nrb + 2 * r;
        wmma::store_matrix_sync(&sX[(nr * 16) * D + nc * 16], cG[r], D, wmma::mem_row_major);
        wmma::store_matrix_sync(&sP[(nr * 16) * D + nc * 16], cP[r], D, wmma::mem_row_major);
    }
    __syncthreads();

    // epilogue: 2 passes, thread = (node 0..31 + 32*pass, colgroup 0..7)
#pragma unroll
    for (int pass = 0; pass < 2; pass++) {
        int ln = (tid >> 3) + 32 * pass;
        int cg = tid & 7;              // 8 cols
        int gn = blockIdx.x * GB + ln;
        if (gn < n) {
            const float4* cg4 = (const float4*)&sX[ln * D + cg * 8];
            const float4* cp4 = (const float4*)&sP[ln * D + cg * 8];
            const float4* bg4 = (const float4*)&bg[cg * 8];
            const float4* bp4 = (const float4*)&bp[cg * 8];
#pragma unroll
            for (int h = 0; h < 2; h++) {
                float4 g4 = cg4[h], p4 = cp4[h], b1 = bg4[h], b2 = bp4[h];
                __half2 h0 = __floats2half2_rn(g4.x, g4.y);
                __half2 h1 = __floats2half2_rn(g4.z, g4.w);
                g_hs[(size_t)gn * 32 + (cg * 2 + h) * 2 + 0] = h0;
                g_hs[(size_t)gn * 32 + (cg * 2 + h) * 2 + 1] = h1;
                float4 o;
                o.x = p4.x + b1.x + b2.x;
                o.y = p4.y + b1.y + b2.y;
                o.z = p4.z + b1.z + b2.z;
                o.w = p4.w + b1.w + b2.w;
                ((float4*)out)[(size_t)gn * 16 + cg * 2 + h] = o;
            }
        }
    }
}

// ---------------------------------------------------------------------------
// Aggregate: one warp per node, TWO edges per load round (R10 shape).
// Per edge: weight = rsqrt(cnt[src]+1), gathered alongside slots.
// Self-loop folded in. Final scale by dinv[dst].
//   out[node] += dinv[dst]*( Σ_src h[src]*dinv[src] + dinv[dst]*h[node] )
__global__ __launch_bounds__(256) void k_agg(float* __restrict__ out, int n) {
    int warp = (blockIdx.x * blockDim.x + threadIdx.x) >> 5;
    int lane = threadIdx.x & 31;
    if (warp >= n) return;

    int cnt = g_cnt[warp];
    int deg = cnt < CAP ? cnt : CAP;
    const int* slots = &g_slot[(size_t)warp * CAP];
    int half  = lane >> 4;
    int sub   = lane & 15;

    const uint2* hs = (const uint2*)g_hs;   // 16 uint2 per node row (128B)
    float4 a = {0.f, 0.f, 0.f, 0.f};

    int j = 0;
    for (; j + 8 <= deg; j += 8) {
        int s[8];
#pragma unroll
        for (int u = 0; u < 8; u++) s[u] = slots[j + u];
        int   e[4];
        float w[4];
#pragma unroll
        for (int u = 0; u < 4; u++) {
            e[u] = half ? s[2 * u + 1] : s[2 * u];
            w[u] = rsqrtf((float)g_cnt[e[u]] + 1.0f);
        }
#pragma unroll
        for (int u = 0; u < 4; u++) {
            uint2 v = hs[(size_t)e[u] * 16 + sub];
            __half2 h0 = *reinterpret_cast<__half2*>(&v.x);
            __half2 h1 = *reinterpret_cast<__half2*>(&v.y);
            float2 f0 = __half22float2(h0);
            float2 f1 = __half22float2(h1);
            a.x = fmaf(w[u], f0.x, a.x);
            a.y = fmaf(w[u], f0.y, a.y);
            a.z = fmaf(w[u], f1.x, a.z);
            a.w = fmaf(w[u], f1.y, a.w);
        }
    }
    for (; j < deg; j += 2) {
        int e0 = slots[j];
        bool has1 = (j + 1 < deg);
        int e1 = has1 ? slots[j + 1] : e0;
        float m = (half == 0 || has1) ? 1.f : 0.f;
        int e = half ? e1 : e0;
        float we = m * rsqrtf((float)g_cnt[e] + 1.0f);
        uint2 v = hs[(size_t)e * 16 + sub];
        __half2 h0 = *reinterpret_cast<__half2*>(&v.x);
        __half2 h1 = *reinterpret_cast<__half2*>(&v.y);
        float2 f0 = __half22float2(h0);
        float2 f1 = __half22float2(h1);
        a.x = fmaf(we, f0.x, a.x);
        a.y = fmaf(we, f0.y, a.y);
        a.z = fmaf(we, f1.x, a.z);
        a.w = fmaf(we, f1.y, a.w);
    }

    a.x += __shfl_xor_sync(0xffffffffu, a.x, 16);
    a.y += __shfl_xor_sync(0xffffffffu, a.y, 16);
    a.z += __shfl_xor_sync(0xffffffffu, a.z, 16);
    a.w += __shfl_xor_sync(0xffffffffu, a.w, 16);

    if (half == 0) {
        float wdst = rsqrtf((float)cnt + 1.0f);
        // self-loop: + wdst * h[own]  (total becomes wdst^2 * h after scale)
        uint2 v = hs[(size_t)warp * 16 + sub];
        __half2 h0 = *reinterpret_cast<__half2*>(&v.x);
        __half2 h1 = *reinterpret_cast<__half2*>(&v.y);
        float2 f0 = __half22float2(h0);
        float2 f1 = __half22float2(h1);
        a.x = fmaf(wdst, f0.x, a.x);
        a.y = fmaf(wdst, f0.y, a.y);
        a.z = fmaf(wdst, f1.x, a.z);
        a.w = fmaf(wdst, f1.y, a.w);

        float4* o = (float4*)out + (size_t)warp * 16 + sub;
        float4 cur = *o;
        cur.x += wdst * a.x;
        cur.y += wdst * a.y;
        cur.z += wdst * a.z;
        cur.w += wdst * a.w;
        *o = cur;
    }
}

// ---------------------------------------------------------------------------
extern "C" void kernel_launch(void* const* d_in, const int* in_sizes, int n_in,
                              void* d_out, int out_size)
{
    // Identify inputs by size pattern (robust to harness reordering).
    int N = 100000, E = 1600000;
    int i_edge = 1;
    int feat[2] = {0, 2}, wmat[2], nw = 0, bias[2], nb = 0;
    for (int i = 0; i < n_in; i++) {
        int s = in_sizes[i];
        if (s == D * D)  { if (nw < 2) wmat[nw++] = i; }
        else if (s == D) { if (nb < 2) bias[nb++] = i; }
    }
    {
        int larges[3], nl = 0;
        for (int i = 0; i < n_in; i++) {
            int s = in_sizes[i];
            if (s != D * D && s != D) { if (nl < 3) larges[nl++] = i; }
        }
        if (nl == 3) {
            int s0 = in_sizes[larges[0]], s1 = in_sizes[larges[1]], s2 = in_sizes[larges[2]];
            int ie;
            if (s0 == s1)      ie = larges[2];
            else if (s0 == s2) ie = larges[1];
            else if (s1 == s2) ie = larges[0];
            else               ie = larges[1];
            i_edge = ie;
            int k = 0;
            for (int j = 0; j < 3; j++) if (larges[j] != ie) feat[k++] = larges[j];
            E = in_sizes[ie] / 2;
            N = in_sizes[feat[0]] / D;
        }
    }

    const float* x   = (const float*)d_in[feat[0]];
    const float* pos = (const float*)d_in[feat[1]];
    const void*  ei  = d_in[i_edge];
    const float* Wg  = (const float*)d_in[wmat[0]];
    const float* Wp  = (const float*)d_in[wmat[1]];
    const float* bg  = (const float*)d_in[bias[0]];
    const float* bp  = (const float*)d_in[bias[1]];
    float*       out = (float*)d_out;

    if (N > NMAX) N = NMAX;
    if (E > EMAX) E = EMAX;

    // One-time resources (created on the uncaptured correctness call).
    static cudaStream_t s2 = nullptr;
    static cudaEvent_t evFork = nullptr, evGemm = nullptr;
    if (s2 == nullptr) {
        cudaStreamCreateWithFlags(&s2, cudaStreamNonBlocking);
        cudaEventCreateWithFlags(&evFork, cudaEventDisableTiming);
        cudaEventCreateWithFlags(&evGemm, cudaEventDisableTiming);
        cudaFuncSetAttribute(k_gemm_pure, cudaFuncAttributeMaxDynamicSharedMemorySize,
                             (int)(16384 * sizeof(float)));
    }

    void* cnt_ptr = nullptr;
    cudaGetSymbolAddress(&cnt_ptr, g_cnt);

    // Fork: gemm (independent of edges) runs on s2, concurrent with memset+fill.
    cudaEventRecord(evFork, 0);
    cudaStreamWaitEvent(s2, evFork, 0);
    k_gemm_pure<<<(N + GB - 1) / GB, 256, 16384 * sizeof(float), s2>>>(
        x, pos, Wg, bg, Wp, bp, out, N);
    cudaEventRecord(evGemm, s2);

    cudaMemsetAsync(cnt_ptr, 0, (size_t)N * sizeof(int));
    k_fill<<<(E + 255) / 256, 256>>>(ei, E, N);

    // Join: agg needs both branches.
    cudaStreamWaitEvent(0, evGemm, 0);
    k_agg<<<(N * 32 + 255) / 256, 256>>>(out, N);
}

// round 14
// speedup vs baseline: 1.1764x; 1.1565x over previous
#include <cuda_runtime.h>
#include <cuda_bf16.h>
#include <cuda_fp16.h>
#include <cstdint>
#include <mma.h>

using namespace nvcuda;

#define D      64
#define SW     68          // padded smem row stride (floats): 4-bank row shift
#define NMAX   100000
#define EMAX   2000000
#define CAP    128         // max slots per node
#define GB     64          // nodes per gemm block

// Scratch (allocation-free rule: __device__ globals)
__device__ __align__(16) __half2 g_hs[(size_t)NMAX * 32];  // h = x@Wg (UNSCALED), fp16
__device__ int g_cnt[NMAX];                 // degree counters / cursors
__device__ int g_slot[(size_t)NMAX * CAP];  // src per edge, bucketed by dst

// ---------------------------------------------------------------------------
__device__ __forceinline__ int clampi(long long v, int n) {
    if (v < 0)  v = 0;
    if (v >= n) v = n - 1;
    return (int)v;
}

// Per-block dtype detect: warp 0 ballots first 256 int64-interpreted values.
__device__ __forceinline__ int block_detect(const void* ei, int E, int n) {
    __shared__ int smode;
    if (threadIdx.x < 32) {
        const long long* p = (const long long*)ei;
        int lim = E < 256 ? E : 256;
        bool bad = false;
        for (int k = threadIdx.x; k < lim; k += 32) {
            long long v = p[k];
            if (v < 0 || v >= (long long)n) bad = true;
        }
        unsigned m = __ballot_sync(0xffffffffu, bad);
        if (threadIdx.x == 0) smode = m ? 1 : 0;
    }
    __syncthreads();
    return smode;
}

// Direct bucket fill (1 edge/thread). Atomic return = slot index.
__global__ void k_fill(const void* __restrict__ ei, int E, int n) {
    int mode = block_detect(ei, E, n);
    int e = blockIdx.x * blockDim.x + threadIdx.x;
    if (e < E) {
        int src, dst;
        if (mode == 0) {
            const long long* p = (const long long*)ei;
            src = clampi(p[e], n);
            dst = clampi(p[(size_t)E + e], n);
        } else {
            const int* p = (const int*)ei;
            src = clampi((long long)p[e], n);
            dst = clampi((long long)p[(size_t)E + e], n);
        }
        int c = atomicAdd(&g_cnt[dst], 1);
        if (c < CAP) g_slot[(size_t)dst * CAP + c] = src;
    }
}

// ---------------------------------------------------------------------------
// Pure dual GEMM (NO dependence on g_cnt -> runs concurrently with k_fill).
// tf32 wmma m16n16k8, 64 nodes/block. All smem tiles use padded stride SW=68
// floats (272B) so fragment column walks shift 4 banks per row (2-way max
// conflict instead of 8-way at stride 256B).
//   h[n]   = x[n] @ Wg                     (stored fp16, unscaled)
//   out[n] = pos[n] @ Wp + b_pos + b_gcn   (conv part added later by k_agg)
__global__ __launch_bounds__(256) void k_gemm_pure(
    const float* __restrict__ x, const float* __restrict__ pos,
    const float* __restrict__ Wg, const float* __restrict__ bg,
    const float* __restrict__ Wp, const float* __restrict__ bp,
    float* __restrict__ out, int n)
{
    extern __shared__ float smem_dyn[];
    float* sWg = smem_dyn;             // 64 rows x SW
    float* sWp = sWg + D * SW;
    float* sX  = sWp + D * SW;         // GB rows x SW
    float* sP  = sX + GB * SW;

    int tid  = threadIdx.x;
    int warp = tid >> 5;

    // stage weights (64 rows x 16 float4), tf32-rounded, padded stride
    {
        const float4* Wg4 = (const float4*)Wg;
        const float4* Wp4 = (const float4*)Wp;
#pragma unroll
        for (int i = 0; i < 4; i++) {
            int idx = tid + 256 * i;        // 0..1023
            int row = idx >> 4;             // k row
            int c4  = idx & 15;
            float4 a = Wg4[idx];
            float4 b = Wp4[idx];
            a.x = wmma::__float_to_tf32(a.x); a.y = wmma::__float_to_tf32(a.y);
            a.z = wmma::__float_to_tf32(a.z); a.w = wmma::__float_to_tf32(a.w);
            b.x = wmma::__float_to_tf32(b.x); b.y = wmma::__float_to_tf32(b.y);
            b.z = wmma::__float_to_tf32(b.z); b.w = wmma::__float_to_tf32(b.w);
            *(float4*)&sWg[row * SW + c4 * 4] = a;
            *(float4*)&sWp[row * SW + c4 * 4] = b;
        }
    }
    // stage inputs, tf32-rounded, padded stride (clamp oob node)
    {
        int base = blockIdx.x * GB;
#pragma unroll
        for (int i = 0; i < 4; i++) {
            int idx = tid + 256 * i;
            int ln  = idx >> 4;             // node 0..63
            int c4  = idx & 15;
            int gn  = base + ln;
            if (gn >= n) gn = n - 1;
            float4 a = ((const float4*)x)[(size_t)gn * 16 + c4];
            float4 b = ((const float4*)pos)[(size_t)gn * 16 + c4];
            a.x = wmma::__float_to_tf32(a.x); a.y = wmma::__float_to_tf32(a.y);
            a.z = wmma::__float_to_tf32(a.z); a.w = wmma::__float_to_tf32(a.w);
            b.x = wmma::__float_to_tf32(b.x); b.y = wmma::__float_to_tf32(b.y);
            b.z = wmma::__float_to_tf32(b.z); b.w = wmma::__float_to_tf32(b.w);
            *(float4*)&sX[ln * SW + c4 * 4] = a;
            *(float4*)&sP[ln * SW + c4 * 4] = b;
        }
    }
    __syncthreads();

    int nrb = warp >> 2;
    int nc  = warp & 3;

    wmma::fragment<wmma::accumulator, 16, 16, 8, float> cG[2], cP[2];
    wmma::fill_fragment(cG[0], 0.0f);
    wmma::fill_fragment(cP[0], 0.0f);
    wmma::fill_fragment(cG[1], 0.0f);
    wmma::fill_fragment(cP[1], 0.0f);

#pragma unroll
    for (int k = 0; k < 8; k++) {
        wmma::fragment<wmma::matrix_b, 16, 16, 8, wmma::precision::tf32, wmma::row_major> bG, bP;
        wmma::load_matrix_sync(bG, &sWg[(k * 8) * SW + nc * 16], SW);
        wmma::load_matrix_sync(bP, &sWp[(k * 8) * SW + nc * 16], SW);
#pragma unroll
        for (int r = 0; r < 2; r++) {
            int nr = nrb + 2 * r;
            wmma::fragment<wmma::matrix_a, 16, 16, 8, wmma::precision::tf32, wmma::row_major> aX, aP;
            wmma::load_matrix_sync(aX, &sX[(nr * 16) * SW + k * 8], SW);
            wmma::load_matrix_sync(aP, &sP[(nr * 16) * SW + k * 8], SW);
            wmma::mma_sync(cG[r], aX, bG, cG[r]);
            wmma::mma_sync(cP[r], aP, bP, cP[r]);
        }
    }

    __syncthreads();   // all input reads done before overwriting with C
#pragma unroll
    for (int r = 0; r < 2; r++) {
        int nr = nrb + 2 * r;
        wmma::store_matrix_sync(&sX[(nr * 16) * SW + nc * 16], cG[r], SW, wmma::mem_row_major);
        wmma::store_matrix_sync(&sP[(nr * 16) * SW + nc * 16], cP[r], SW, wmma::mem_row_major);
    }
    __syncthreads();

    // epilogue: 2 passes, thread = (node 0..31 + 32*pass, colgroup 0..7)
#pragma unroll
    for (int pass = 0; pass < 2; pass++) {
        int ln = (tid >> 3) + 32 * pass;
        int cg = tid & 7;              // 8 cols
        int gn = blockIdx.x * GB + ln;
        if (gn < n) {
            const float4* bg4 = (const float4*)&bg[cg * 8];
            const float4* bp4 = (const float4*)&bp[cg * 8];
#pragma unroll
            for (int h = 0; h < 2; h++) {
                float4 g4 = *(const float4*)&sX[ln * SW + cg * 8 + h * 4];
                float4 p4 = *(const float4*)&sP[ln * SW + cg * 8 + h * 4];
                float4 b1 = bg4[h], b2 = bp4[h];
                __half2 h0 = __floats2half2_rn(g4.x, g4.y);
                __half2 h1 = __floats2half2_rn(g4.z, g4.w);
                g_hs[(size_t)gn * 32 + (cg * 2 + h) * 2 + 0] = h0;
                g_hs[(size_t)gn * 32 + (cg * 2 + h) * 2 + 1] = h1;
                float4 o;
                o.x = p4.x + b1.x + b2.x;
                o.y = p4.y + b1.y + b2.y;
                o.z = p4.z + b1.z + b2.z;
                o.w = p4.w + b1.w + b2.w;
                ((float4*)out)[(size_t)gn * 16 + cg * 2 + h] = o;
            }
        }
    }
}

// ---------------------------------------------------------------------------
// Aggregate: one warp per node, TWO edges per load round.
// Per edge: weight = rsqrt(cnt[src]+1), gathered alongside slots.
// Self-loop folded in. Final scale by dinv[dst].
//   out[node] += dinv[dst]*( Σ_src h[src]*dinv[src] + dinv[dst]*h[node] )
__global__ __launch_bounds__(256) void k_agg(float* __restrict__ out, int n) {
    int warp = (blockIdx.x * blockDim.x + threadIdx.x) >> 5;
    int lane = threadIdx.x & 31;
    if (warp >= n) return;

    int cnt = g_cnt[warp];
    int deg = cnt < CAP ? cnt : CAP;
    const int* slots = &g_slot[(size_t)warp * CAP];
    int half  = lane >> 4;
    int sub   = lane & 15;

    const uint2* hs = (const uint2*)g_hs;   // 16 uint2 per node row (128B)
    float4 a = {0.f, 0.f, 0.f, 0.f};

    int j = 0;
    for (; j + 8 <= deg; j += 8) {
        int s[8];
#pragma unroll
        for (int u = 0; u < 8; u++) s[u] = slots[j + u];
        int   e[4];
        float w[4];
#pragma unroll
        for (int u = 0; u < 4; u++) {
            e[u] = half ? s[2 * u + 1] : s[2 * u];
            w[u] = rsqrtf((float)g_cnt[e[u]] + 1.0f);
        }
#pragma unroll
        for (int u = 0; u < 4; u++) {
            uint2 v = hs[(size_t)e[u] * 16 + sub];
            __half2 h0 = *reinterpret_cast<__half2*>(&v.x);
            __half2 h1 = *reinterpret_cast<__half2*>(&v.y);
            float2 f0 = __half22float2(h0);
            float2 f1 = __half22float2(h1);
            a.x = fmaf(w[u], f0.x, a.x);
            a.y = fmaf(w[u], f0.y, a.y);
            a.z = fmaf(w[u], f1.x, a.z);
            a.w = fmaf(w[u], f1.y, a.w);
        }
    }
    for (; j < deg; j += 2) {
        int e0 = slots[j];
        bool has1 = (j + 1 < deg);
        int e1 = has1 ? slots[j + 1] : e0;
        float m = (half == 0 || has1) ? 1.f : 0.f;
        int e = half ? e1 : e0;
        float we = m * rsqrtf((float)g_cnt[e] + 1.0f);
        uint2 v = hs[(size_t)e * 16 + sub];
        __half2 h0 = *reinterpret_cast<__half2*>(&v.x);
        __half2 h1 = *reinterpret_cast<__half2*>(&v.y);
        float2 f0 = __half22float2(h0);
        float2 f1 = __half22float2(h1);
        a.x = fmaf(we, f0.x, a.x);
        a.y = fmaf(we, f0.y, a.y);
        a.z = fmaf(we, f1.x, a.z);
        a.w = fmaf(we, f1.y, a.w);
    }

    a.x += __shfl_xor_sync(0xffffffffu, a.x, 16);
    a.y += __shfl_xor_sync(0xffffffffu, a.y, 16);
    a.z += __shfl_xor_sync(0xffffffffu, a.z, 16);
    a.w += __shfl_xor_sync(0xffffffffu, a.w, 16);

    if (half == 0) {
        float wdst = rsqrtf((float)cnt + 1.0f);
        // self-loop: + wdst * h[own]  (total becomes wdst^2 * h after scale)
        uint2 v = hs[(size_t)warp * 16 + sub];
        __half2 h0 = *reinterpret_cast<__half2*>(&v.x);
        __half2 h1 = *reinterpret_cast<__half2*>(&v.y);
        float2 f0 = __half22float2(h0);
        float2 f1 = __half22float2(h1);
        a.x = fmaf(wdst, f0.x, a.x);
        a.y = fmaf(wdst, f0.y, a.y);
        a.z = fmaf(wdst, f1.x, a.z);
        a.w = fmaf(wdst, f1.y, a.w);

        float4* o = (float4*)out + (size_t)warp * 16 + sub;
        float4 cur = *o;
        cur.x += wdst * a.x;
        cur.y += wdst * a.y;
        cur.z += wdst * a.z;
        cur.w += wdst * a.w;
        *o = cur;
    }
}

// ---------------------------------------------------------------------------
extern "C" void kernel_launch(void* const* d_in, const int* in_sizes, int n_in,
                              void* d_out, int out_size)
{
    // Identify inputs by size pattern (robust to harness reordering).
    int N = 100000, E = 1600000;
    int i_edge = 1;
    int feat[2] = {0, 2}, wmat[2], nw = 0, bias[2], nb = 0;
    for (int i = 0; i < n_in; i++) {
        int s = in_sizes[i];
        if (s == D * D)  { if (nw < 2) wmat[nw++] = i; }
        else if (s == D) { if (nb < 2) bias[nb++] = i; }
    }
    {
        int larges[3], nl = 0;
        for (int i = 0; i < n_in; i++) {
            int s = in_sizes[i];
            if (s != D * D && s != D) { if (nl < 3) larges[nl++] = i; }
        }
        if (nl == 3) {
            int s0 = in_sizes[larges[0]], s1 = in_sizes[larges[1]], s2 = in_sizes[larges[2]];
            int ie;
            if (s0 == s1)      ie = larges[2];
            else if (s0 == s2) ie = larges[1];
            else if (s1 == s2) ie = larges[0];
            else               ie = larges[1];
            i_edge = ie;
            int k = 0;
            for (int j = 0; j < 3; j++) if (larges[j] != ie) feat[k++] = larges[j];
            E = in_sizes[ie] / 2;
            N = in_sizes[feat[0]] / D;
        }
    }

    const float* x   = (const float*)d_in[feat[0]];
    const float* pos = (const float*)d_in[feat[1]];
    const void*  ei  = d_in[i_edge];
    const float* Wg  = (const float*)d_in[wmat[0]];
    const float* Wp  = (const float*)d_in[wmat[1]];
    const float* bg  = (const float*)d_in[bias[0]];
    const float* bp  = (const float*)d_in[bias[1]];
    float*       out = (float*)d_out;

    if (N > NMAX) N = NMAX;
    if (E > EMAX) E = EMAX;

    const int GEMM_SMEM = (2 * D * SW + 2 * GB * SW) * (int)sizeof(float); // 69632B

    // One-time resources (created on the uncaptured correctness call).
    static cudaStream_t s2 = nullptr;
    static cudaEvent_t evFork = nullptr, evGemm = nullptr;
    if (s2 == nullptr) {
        cudaStreamCreateWithFlags(&s2, cudaStreamNonBlocking);
        cudaEventCreateWithFlags(&evFork, cudaEventDisableTiming);
        cudaEventCreateWithFlags(&evGemm, cudaEventDisableTiming);
        cudaFuncSetAttribute(k_gemm_pure, cudaFuncAttributeMaxDynamicSharedMemorySize,
                             GEMM_SMEM);
    }

    void* cnt_ptr = nullptr;
    cudaGetSymbolAddress(&cnt_ptr, g_cnt);

    // Fork: gemm (independent of edges) runs on s2, concurrent with memset+fill.
    cudaEventRecord(evFork, 0);
    cudaStreamWaitEvent(s2, evFork, 0);
    k_gemm_pure<<<(N + GB - 1) / GB, 256, GEMM_SMEM, s2>>>(
        x, pos, Wg, bg, Wp, bp, out, N);
    cudaEventRecord(evGemm, s2);

    cudaMemsetAsync(cnt_ptr, 0, (size_t)N * sizeof(int));
    k_fill<<<(E + 255) / 256, 256>>>(ei, E, N);

    // Join: agg needs both branches.
    cudaStreamWaitEvent(0, evGemm, 0);
    k_agg<<<(N * 32 + 255) / 256, 256>>>(out, N);
}